// round 7
// baseline (speedup 1.0000x reference)
#include <cuda_runtime.h>

// SPConv fused GNN, R7: R6 design (constant-mem weights, 2 CTA/SM, vec4 red)
// with the pack2 PTX typo fixed.

#define TPB 512
// edge kernel tiling
#define TE_E 128
#define APE 132
// pq/out kernel tiling (R5 layout)
#define TE_N 256
#define APN 260

typedef unsigned long long ull;

__device__ float g_cnt[65536];
__device__ int g_idx64;
__device__ float g_P[3276800];   // z @ Wm1[0:64]
__device__ float g_Q[3276800];   // z @ Wm1[64:128]

__constant__ float cWe1[3 * 64];
__constant__ float cWe2[64 * 64];
__constant__ float cWm1c[64 * 64];   // Wm1 rows 128..191
__constant__ float cWm2[64 * 64];
__constant__ float cbe1[64], cbe2[64], cbm1[64], cbm2[64];

__device__ __forceinline__ void ffma2(ull& acc, ull a, ull b) {
    asm("fma.rn.f32x2 %0, %1, %2, %0;" : "+l"(acc) : "l"(a), "l"(b));
}
__device__ __forceinline__ ull dup2(float w) {
    ull r;
    asm("mov.b64 %0, {%1, %1};" : "=l"(r) : "r"(__float_as_uint(w)));
    return r;
}
__device__ __forceinline__ ull pack2(float lo, float hi) {
    ull r;
    asm("mov.b64 %0, {%1, %2};" : "=l"(r)
        : "r"(__float_as_uint(lo)), "r"(__float_as_uint(hi)));
    return r;
}
__device__ __forceinline__ void unpack2(ull v, float& lo, float& hi) {
    unsigned a, b;
    asm("mov.b64 {%0, %1}, %2;" : "=r"(a), "=r"(b) : "l"(v));
    lo = __uint_as_float(a);
    hi = __uint_as_float(b);
}
__device__ __forceinline__ void red_add_v4(float* p, float x, float y,
                                           float z, float w) {
    asm volatile("red.global.add.v4.f32 [%0], {%1, %2, %3, %4};"
                 :: "l"(p), "f"(x), "f"(y), "f"(z), "f"(w) : "memory");
}

__global__ void detect_kernel(const unsigned long long* __restrict__ ei) {
    if (threadIdx.x == 0 && blockIdx.x == 0) {
        int is64 = 1;
        for (int i = 0; i < 64; ++i)
            if ((ei[i] >> 32) != 0ull) { is64 = 0; break; }
        g_idx64 = is64;
    }
}

__global__ void zero_kernel(float* __restrict__ sums, int total, int n) {
    int i = blockIdx.x * blockDim.x + threadIdx.x;
    if (i < total) sums[i] = 0.0f;
    if (i < n) g_cnt[i] = 0.0f;
}

// ======== edge-kernel GEMM: 4 channels (2 pairs) x 4 edges, W in constant ====
__device__ __forceinline__ void egemm(const float* __restrict__ H,
                                      const float* __restrict__ Wc, int K,
                                      int cb, int eb, ull acc[2][4]) {
#pragma unroll 8
    for (int k = 0; k < K; ++k) {
        ulonglong2 w = *reinterpret_cast<const ulonglong2*>(Wc + k * 64 + cb);
        float4 h = *reinterpret_cast<const float4*>(H + k * APE + eb);
        ull h2[4] = {dup2(h.x), dup2(h.y), dup2(h.z), dup2(h.w)};
#pragma unroll
        for (int e = 0; e < 4; ++e) {
            ffma2(acc[0][e], w.x, h2[e]);
            ffma2(acc[1][e], w.y, h2[e]);
        }
    }
}

__device__ __forceinline__ void ezero(ull acc[2][4]) {
#pragma unroll
    for (int cp = 0; cp < 2; ++cp)
#pragma unroll
        for (int e = 0; e < 4; ++e) acc[cp][e] = 0ull;
}

// relu(acc + bias) -> D[ch][eb..eb+3], 4 dense STS.128
__device__ __forceinline__ void estore_relu(float* __restrict__ D,
                                            ull acc[2][4],
                                            const float* __restrict__ bias,
                                            int cb, int eb) {
#pragma unroll
    for (int cp = 0; cp < 2; ++cp) {
        float lo[4], hi[4];
#pragma unroll
        for (int e = 0; e < 4; ++e) unpack2(acc[cp][e], lo[e], hi[e]);
        float b0 = bias[cb + 2 * cp], b1 = bias[cb + 2 * cp + 1];
        float4 v0, v1;
        v0.x = fmaxf(lo[0] + b0, 0.0f); v0.y = fmaxf(lo[1] + b0, 0.0f);
        v0.z = fmaxf(lo[2] + b0, 0.0f); v0.w = fmaxf(lo[3] + b0, 0.0f);
        v1.x = fmaxf(hi[0] + b1, 0.0f); v1.y = fmaxf(hi[1] + b1, 0.0f);
        v1.z = fmaxf(hi[2] + b1, 0.0f); v1.w = fmaxf(hi[3] + b1, 0.0f);
        *reinterpret_cast<float4*>(D + (cb + 2 * cp) * APE + eb) = v0;
        *reinterpret_cast<float4*>(D + (cb + 2 * cp + 1) * APE + eb) = v1;
    }
}

// ======== edge_kernel ========
// smem floats:  0: sDelta 3*APE=396 | 396: sA 64*APE=8448 | 8844: sB 8448
//               17292: src/dst 2*TE_E ints
__global__ __launch_bounds__(TPB, 2) void edge_kernel(
    const float* __restrict__ cent, const void* __restrict__ ei_raw,
    float* __restrict__ sums, int E, int N, int ntiles) {
    extern __shared__ float sm[];
    float* sDelta = sm;
    float* sA = sm + 396;
    float* sB = sm + 8844;
    int* sSrc = (int*)(sm + 17292);
    int* sDst = sSrc + TE_E;

    const int tid = threadIdx.x;
    const int idx64 = g_idx64;
    const long long* ei64 = (const long long*)ei_raw;
    const int* ei32 = (const int*)ei_raw;

    const int wid = tid >> 5, lane = tid & 31;
    const int cb = wid * 4;        // 16 warps x 4 channels = 64
    const int eb = lane * 4;       // 32 lanes x 4 edges = 128

    for (int tile = blockIdx.x; tile < ntiles; tile += gridDim.x) {
        const int base = tile * TE_E;

        if (tid < TE_E) {
            int e = base + tid;
            int s = 0, d = -1;
            if (e < E) {
                if (idx64) { s = (int)ei64[e]; d = (int)ei64[(size_t)E + e]; }
                else       { s = ei32[e];      d = ei32[E + e]; }
                if (s < 0 || s >= N) s = 0;
                if (d < 0 || d >= N) d = 0;
            }
            sSrc[tid] = s;
            sDst[tid] = d;
        }
        __syncthreads();

        if (tid < 3 * TE_E) {
            int e = tid & (TE_E - 1), comp = tid >> 7;
            int s = sSrc[e], d = sDst[e];
            int dd = (d < 0) ? s : d;
            sDelta[comp * APE + e] =
                cent[(size_t)dd * 3 + comp] - cent[(size_t)s * 3 + comp];
        }
        __syncthreads();

        ull acc[2][4];

        // L1: e1 = relu(delta @ We1 + be1) -> sA
        ezero(acc);
        egemm(sDelta, cWe1, 3, cb, eb, acc);
        estore_relu(sA, acc, cbe1, cb, eb);
        __syncthreads();

        // L2: e = relu(e1 @ We2 + be2) -> sB
        ezero(acc);
        egemm(sA, cWe2, 64, cb, eb, acc);
        estore_relu(sB, acc, cbe2, cb, eb);
        __syncthreads();

        // L3: m1 = relu(e @ Wm1c + P[src] + Q[dst] + bm1) -> sA
#pragma unroll
        for (int e = 0; e < 4; ++e) {
            int ed = eb + e;
            int s = sSrc[ed], d = sDst[ed];
            int dd = (d < 0) ? s : d;
            float4 p = *reinterpret_cast<const float4*>(&g_P[(size_t)s * 64 + cb]);
            float4 q = *reinterpret_cast<const float4*>(&g_Q[(size_t)dd * 64 + cb]);
            acc[0][e] = pack2(p.x + q.x, p.y + q.y);
            acc[1][e] = pack2(p.z + q.z, p.w + q.w);
        }
        egemm(sB, cWm1c, 64, cb, eb, acc);
        estore_relu(sA, acc, cbm1, cb, eb);
        __syncthreads();

        // L4: m = m1 @ Wm2 + bm2 -> vec4 scatter-add to sums[dst]
        ezero(acc);
        egemm(sA, cWm2, 64, cb, eb, acc);
#pragma unroll
        for (int e = 0; e < 4; ++e) {
            int d = sDst[eb + e];
            if (d >= 0) {
                float l0, h0, l1, h1;
                unpack2(acc[0][e], l0, h0);
                unpack2(acc[1][e], l1, h1);
                red_add_v4(&sums[(size_t)d * 64 + cb],
                           l0 + cbm2[cb], h0 + cbm2[cb + 1],
                           l1 + cbm2[cb + 2], h1 + cbm2[cb + 3]);
            }
        }
        if (tid < TE_E && sDst[tid] >= 0) atomicAdd(&g_cnt[sDst[tid]], 1.0f);
        __syncthreads();
    }
}

// ======== R5-style 8ch x 4edge smem-weight GEMM for pq/out kernels ========
__device__ __forceinline__ void gemmp(const float* __restrict__ H, int hp,
                                      const float* __restrict__ W, int K,
                                      int cb, int eb, ull acc[4][4]) {
#pragma unroll 4
    for (int k = 0; k < K; ++k) {
        ulonglong2 wA = *reinterpret_cast<const ulonglong2*>(W + k * 64 + cb);
        ulonglong2 wB = *reinterpret_cast<const ulonglong2*>(W + k * 64 + cb + 4);
        ull w2[4] = {wA.x, wA.y, wB.x, wB.y};
        float4 h = *reinterpret_cast<const float4*>(H + k * hp + eb);
        ull h2[4] = {dup2(h.x), dup2(h.y), dup2(h.z), dup2(h.w)};
#pragma unroll
        for (int cp = 0; cp < 4; ++cp)
#pragma unroll
            for (int e = 0; e < 4; ++e)
                ffma2(acc[cp][e], w2[cp], h2[e]);
    }
}

__device__ __forceinline__ void zero_acc(ull acc[4][4]) {
#pragma unroll
    for (int cp = 0; cp < 4; ++cp)
#pragma unroll
        for (int e = 0; e < 4; ++e) acc[cp][e] = 0ull;
}

// ---- pq_kernel: P = z @ Wm1[0:64], Q = z @ Wm1[64:128] ----
// smem: sW 8192 | sZ 64*APN=16640  -> 24832 floats
__global__ __launch_bounds__(TPB) void pq_kernel(
    const float* __restrict__ z, const float* __restrict__ Wm1,
    int N, int ntiles) {
    extern __shared__ float sm[];
    float* sW = sm;
    float* sZ = sm + 8192;
    const int tid = threadIdx.x;
    for (int i = tid; i < 8192; i += TPB) sW[i] = Wm1[i];
    __syncthreads();

    const int wid = tid >> 5, lane = tid & 31;
    const int grp = wid >> 3;
    const int cb = (wid & 7) * 8;
    const int eb = grp * 128 + lane * 4;

    for (int tile = blockIdx.x; tile < ntiles; tile += gridDim.x) {
        const int base = tile * TE_N;
        for (int i = tid; i < 64 * TE_N; i += TPB) {
            int nl = i >> 6, k = i & 63;
            int gn = base + nl;
            sZ[k * APN + nl] = (gn < N) ? z[(size_t)gn * 64 + k] : 0.0f;
        }
        __syncthreads();

        ull acc[4][4];
#pragma unroll
        for (int pass = 0; pass < 2; ++pass) {
            zero_acc(acc);
            gemmp(sZ, APN, sW + pass * 64 * 64, 64, cb, eb, acc);
            float* dst = pass == 0 ? g_P : g_Q;
#pragma unroll
            for (int e = 0; e < 4; ++e) {
                int gn = base + eb + e;
                if (gn < N) {
                    float v[8];
#pragma unroll
                    for (int cp = 0; cp < 4; ++cp)
                        unpack2(acc[cp][e], v[2 * cp], v[2 * cp + 1]);
                    *reinterpret_cast<float4*>(&dst[(size_t)gn * 64 + cb]) =
                        make_float4(v[0], v[1], v[2], v[3]);
                    *reinterpret_cast<float4*>(&dst[(size_t)gn * 64 + cb + 4]) =
                        make_float4(v[4], v[5], v[6], v[7]);
                }
            }
        }
        __syncthreads();
    }
}

// ---- out_kernel: out = relu([z, sums/cnt] @ Wu1 + bu1) (in-place on sums) ----
// smem: sW 8192 | sb 64 | sZM 128*APN = 33280 -> 41536 floats
__global__ __launch_bounds__(TPB) void out_kernel(
    const float* __restrict__ z, const float* __restrict__ sums,
    const float* __restrict__ Wu1, const float* __restrict__ bu1,
    float* __restrict__ out, int N, int ntiles) {
    extern __shared__ float sm[];
    float* sW = sm;
    float* sb = sm + 8192;
    float* sZM = sm + 8256;

    const int tid = threadIdx.x;
    for (int i = tid; i < 8192; i += TPB) sW[i] = Wu1[i];
    if (tid < 64) sb[tid] = bu1[tid];
    __syncthreads();

    const int wid = tid >> 5, lane = tid & 31;
    const int grp = wid >> 3;
    const int cb = (wid & 7) * 8;
    const int eb = grp * 128 + lane * 4;

    for (int tile = blockIdx.x; tile < ntiles; tile += gridDim.x) {
        const int base = tile * TE_N;
        for (int i = tid; i < 128 * TE_N; i += TPB) {
            int nl = i >> 7, k = i & 127;
            int gn = base + nl;
            float v = 0.0f;
            if (gn < N) {
                if (k < 64) {
                    v = z[(size_t)gn * 64 + k];
                } else {
                    float c = fmaxf(g_cnt[gn], 1.0f);
                    v = sums[(size_t)gn * 64 + (k - 64)] / c;
                }
            }
            sZM[k * APN + nl] = v;
        }
        __syncthreads();

        ull acc[4][4];
        zero_acc(acc);
        gemmp(sZM, APN, sW, 128, cb, eb, acc);

#pragma unroll
        for (int e = 0; e < 4; ++e) {
            int gn = base + eb + e;
            if (gn < N) {
                float v[8];
#pragma unroll
                for (int cp = 0; cp < 4; ++cp)
                    unpack2(acc[cp][e], v[2 * cp], v[2 * cp + 1]);
                float4 o0, o1;
                o0.x = fmaxf(v[0] + sb[cb + 0], 0.0f);
                o0.y = fmaxf(v[1] + sb[cb + 1], 0.0f);
                o0.z = fmaxf(v[2] + sb[cb + 2], 0.0f);
                o0.w = fmaxf(v[3] + sb[cb + 3], 0.0f);
                o1.x = fmaxf(v[4] + sb[cb + 4], 0.0f);
                o1.y = fmaxf(v[5] + sb[cb + 5], 0.0f);
                o1.z = fmaxf(v[6] + sb[cb + 6], 0.0f);
                o1.w = fmaxf(v[7] + sb[cb + 7], 0.0f);
                *reinterpret_cast<float4*>(&out[(size_t)gn * 64 + cb]) = o0;
                *reinterpret_cast<float4*>(&out[(size_t)gn * 64 + cb + 4]) = o1;
            }
        }
        __syncthreads();
    }
}

extern "C" void kernel_launch(void* const* d_in, const int* in_sizes, int n_in,
                              void* d_out, int out_size) {
    const float* z    = (const float*)d_in[0];
    const float* cent = (const float*)d_in[1];
    const void* ei    = d_in[2];
    const float* We1 = (const float*)d_in[3];
    const float* be1 = (const float*)d_in[4];
    const float* We2 = (const float*)d_in[5];
    const float* be2 = (const float*)d_in[6];
    const float* Wm1 = (const float*)d_in[7];
    const float* bm1 = (const float*)d_in[8];
    const float* Wm2 = (const float*)d_in[9];
    const float* bm2 = (const float*)d_in[10];
    const float* Wu1 = (const float*)d_in[11];
    const float* bu1 = (const float*)d_in[12];
    float* out = (float*)d_out;

    const int N = in_sizes[0] / 64;
    const int E = in_sizes[2] / 2;
    const int ntiles_e = (E + TE_E - 1) / TE_E;
    const int ntiles_n = (N + TE_N - 1) / TE_N;

    // weights -> constant memory (async DtoD, graph-capturable)
    cudaMemcpyToSymbolAsync(cWe1, We1, 3 * 64 * 4, 0, cudaMemcpyDeviceToDevice, 0);
    cudaMemcpyToSymbolAsync(cWe2, We2, 64 * 64 * 4, 0, cudaMemcpyDeviceToDevice, 0);
    cudaMemcpyToSymbolAsync(cWm1c, Wm1 + 128 * 64, 64 * 64 * 4, 0,
                            cudaMemcpyDeviceToDevice, 0);
    cudaMemcpyToSymbolAsync(cWm2, Wm2, 64 * 64 * 4, 0, cudaMemcpyDeviceToDevice, 0);
    cudaMemcpyToSymbolAsync(cbe1, be1, 64 * 4, 0, cudaMemcpyDeviceToDevice, 0);
    cudaMemcpyToSymbolAsync(cbe2, be2, 64 * 4, 0, cudaMemcpyDeviceToDevice, 0);
    cudaMemcpyToSymbolAsync(cbm1, bm1, 64 * 4, 0, cudaMemcpyDeviceToDevice, 0);
    cudaMemcpyToSymbolAsync(cbm2, bm2, 64 * 4, 0, cudaMemcpyDeviceToDevice, 0);

    const size_t smem_edge = 17292 * sizeof(float) + 2 * TE_E * sizeof(int);
    const size_t smem_pq   = 24832 * sizeof(float);
    const size_t smem_out  = 41536 * sizeof(float);

    cudaFuncSetAttribute(edge_kernel, cudaFuncAttributeMaxDynamicSharedMemorySize,
                         (int)smem_edge);
    cudaFuncSetAttribute(pq_kernel, cudaFuncAttributeMaxDynamicSharedMemorySize,
                         (int)smem_pq);
    cudaFuncSetAttribute(out_kernel, cudaFuncAttributeMaxDynamicSharedMemorySize,
                         (int)smem_out);

    detect_kernel<<<1, 32>>>((const unsigned long long*)ei);
    zero_kernel<<<(N * 64 + 255) / 256, 256>>>(out, N * 64, N);
    pq_kernel<<<ntiles_n, TPB, smem_pq>>>(z, Wm1, N, ntiles_n);
    edge_kernel<<<296, TPB, smem_edge>>>(cent, ei, out, E, N, ntiles_e);
    out_kernel<<<ntiles_n, TPB, smem_out>>>(z, out, Wu1, bu1, out, N, ntiles_n);
}

// round 8
// speedup vs baseline: 1.8566x; 1.8566x over previous
#include <cuda_runtime.h>

// SPConv fused GNN, R8: R5 smem-weight GEMM core, L4 GEMM moved to node side
// (scatter m1, apply Wm2 per-node), red.v4 scatter, early PQ acc-init.

#define TPB 512
#define TE 256        // edges (or nodes) per tile
#define AP 260        // activation smem pitch (floats, mult of 4)

typedef unsigned long long ull;

__device__ float g_cnt[65536];
__device__ int g_idx64;
__device__ float g_P[3276800];   // z @ Wm1[0:64]
__device__ float g_Q[3276800];   // z @ Wm1[64:128]

__device__ __forceinline__ void ffma2(ull& acc, ull a, ull b) {
    asm("fma.rn.f32x2 %0, %1, %2, %0;" : "+l"(acc) : "l"(a), "l"(b));
}
__device__ __forceinline__ ull dup2(float w) {
    ull r;
    asm("mov.b64 %0, {%1, %1};" : "=l"(r) : "r"(__float_as_uint(w)));
    return r;
}
__device__ __forceinline__ ull pack2(float lo, float hi) {
    ull r;
    asm("mov.b64 %0, {%1, %2};" : "=l"(r)
        : "r"(__float_as_uint(lo)), "r"(__float_as_uint(hi)));
    return r;
}
__device__ __forceinline__ void unpack2(ull v, float& lo, float& hi) {
    unsigned a, b;
    asm("mov.b64 {%0, %1}, %2;" : "=r"(a), "=r"(b) : "l"(v));
    lo = __uint_as_float(a);
    hi = __uint_as_float(b);
}
__device__ __forceinline__ void red_add_v4(float* p, float x, float y,
                                           float z, float w) {
    asm volatile("red.global.add.v4.f32 [%0], {%1, %2, %3, %4};"
                 :: "l"(p), "f"(x), "f"(y), "f"(z), "f"(w) : "memory");
}
#define GROUP_BAR(g) asm volatile("bar.sync %0, 256;" :: "r"((g) + 1) : "memory")

__global__ void detect_kernel(const unsigned long long* __restrict__ ei) {
    if (threadIdx.x == 0 && blockIdx.x == 0) {
        int is64 = 1;
        for (int i = 0; i < 64; ++i)
            if ((ei[i] >> 32) != 0ull) { is64 = 0; break; }
        g_idx64 = is64;
    }
}

__global__ void zero_kernel(float* __restrict__ sums, int total, int n) {
    int i = blockIdx.x * blockDim.x + threadIdx.x;
    if (i < total) sums[i] = 0.0f;
    if (i < n) g_cnt[i] = 0.0f;
}

// acc[4 ch-pairs][4 edges] += W[k][cb..cb+7] * H[k][eb..eb+3]
// W: smem row-major [K][64] (warp-broadcast loads), H: [K][hp] (dense float4).
__device__ __forceinline__ void gemmp(const float* __restrict__ H, int hp,
                                      const float* __restrict__ W, int K,
                                      int cb, int eb, ull acc[4][4]) {
#pragma unroll 4
    for (int k = 0; k < K; ++k) {
        ulonglong2 wA = *reinterpret_cast<const ulonglong2*>(W + k * 64 + cb);
        ulonglong2 wB = *reinterpret_cast<const ulonglong2*>(W + k * 64 + cb + 4);
        ull w2[4] = {wA.x, wA.y, wB.x, wB.y};
        float4 h = *reinterpret_cast<const float4*>(H + k * hp + eb);
        ull h2[4] = {dup2(h.x), dup2(h.y), dup2(h.z), dup2(h.w)};
#pragma unroll
        for (int cp = 0; cp < 4; ++cp)
#pragma unroll
            for (int e = 0; e < 4; ++e)
                ffma2(acc[cp][e], w2[cp], h2[e]);
    }
}

__device__ __forceinline__ void zero_acc(ull acc[4][4]) {
#pragma unroll
    for (int cp = 0; cp < 4; ++cp)
#pragma unroll
        for (int e = 0; e < 4; ++e) acc[cp][e] = 0ull;
}

// relu(acc + bias) -> D[ch][eb..eb+3] dense float4 rows
__device__ __forceinline__ void store_relu(float* __restrict__ D,
                                           ull acc[4][4],
                                           const float* __restrict__ bias,
                                           int cb, int eb) {
#pragma unroll
    for (int cp = 0; cp < 4; ++cp) {
        float lo[4], hi[4];
#pragma unroll
        for (int e = 0; e < 4; ++e) unpack2(acc[cp][e], lo[e], hi[e]);
        float b0 = bias[cb + 2 * cp], b1 = bias[cb + 2 * cp + 1];
        float4 v0, v1;
        v0.x = fmaxf(lo[0] + b0, 0.0f); v0.y = fmaxf(lo[1] + b0, 0.0f);
        v0.z = fmaxf(lo[2] + b0, 0.0f); v0.w = fmaxf(lo[3] + b0, 0.0f);
        v1.x = fmaxf(hi[0] + b1, 0.0f); v1.y = fmaxf(hi[1] + b1, 0.0f);
        v1.z = fmaxf(hi[2] + b1, 0.0f); v1.w = fmaxf(hi[3] + b1, 0.0f);
        *reinterpret_cast<float4*>(D + (cb + 2 * cp) * AP + eb) = v0;
        *reinterpret_cast<float4*>(D + (cb + 2 * cp + 1) * AP + eb) = v1;
    }
}

// ---- pq_kernel: P = z @ Wm1[0:64], Q = z @ Wm1[64:128] ----
// smem: sW 8192 | sZ 64*AP=16640  -> 24832 floats
__global__ __launch_bounds__(TPB) void pq_kernel(
    const float* __restrict__ z, const float* __restrict__ Wm1,
    int N, int ntiles) {
    extern __shared__ float sm[];
    float* sW = sm;
    float* sZ = sm + 8192;
    const int tid = threadIdx.x;
    for (int i = tid; i < 8192; i += TPB) sW[i] = Wm1[i];
    __syncthreads();

    const int wid = tid >> 5, lane = tid & 31;
    const int grp = wid >> 3;
    const int cb = (wid & 7) * 8;
    const int eb = grp * 128 + lane * 4;

    for (int tile = blockIdx.x; tile < ntiles; tile += gridDim.x) {
        const int base = tile * TE;
        for (int i = tid; i < 64 * TE; i += TPB) {
            int nl = i >> 6, k = i & 63;
            int gn = base + nl;
            sZ[k * AP + nl] = (gn < N) ? z[(size_t)gn * 64 + k] : 0.0f;
        }
        __syncthreads();

        ull acc[4][4];
#pragma unroll
        for (int pass = 0; pass < 2; ++pass) {
            zero_acc(acc);
            gemmp(sZ, AP, sW + pass * 64 * 64, 64, cb, eb, acc);
            float* dst = pass == 0 ? g_P : g_Q;
#pragma unroll
            for (int e = 0; e < 4; ++e) {
                int gn = base + eb + e;
                if (gn < N) {
                    float v[8];
#pragma unroll
                    for (int cp = 0; cp < 4; ++cp)
                        unpack2(acc[cp][e], v[2 * cp], v[2 * cp + 1]);
                    *reinterpret_cast<float4*>(&dst[(size_t)gn * 64 + cb]) =
                        make_float4(v[0], v[1], v[2], v[3]);
                    *reinterpret_cast<float4*>(&dst[(size_t)gn * 64 + cb + 4]) =
                        make_float4(v[4], v[5], v[6], v[7]);
                }
            }
        }
        __syncthreads();
    }
}

// ======== edge_kernel ========
// smem floats:
//      0 : sWe2  4096
//   4096 : sWm1c 4096  (Wm1 rows 128..191)
//   8192 : sWe1   192
//   8384 : be1 64 | 8448 : be2 64 | 8512 : bm1 64
//   8576 : sDelta 3*AP = 780
//   9356 : sA 64*AP = 16640
//  25996 : sB 16640
//  42636 : src/dst (2*TE ints)
__global__ __launch_bounds__(TPB) void edge_kernel(
    const float* __restrict__ cent, const void* __restrict__ ei_raw,
    const float* __restrict__ We1, const float* __restrict__ be1,
    const float* __restrict__ We2, const float* __restrict__ be2,
    const float* __restrict__ Wm1, const float* __restrict__ bm1,
    float* __restrict__ S1, int E, int N, int ntiles) {
    extern __shared__ float sm[];
    float* sWe2 = sm;
    float* sWm1c = sm + 4096;
    float* sWe1 = sm + 8192;
    float* sbe1 = sm + 8384;
    float* sbe2 = sm + 8448;
    float* sbm1 = sm + 8512;
    float* sDelta = sm + 8576;
    float* sA = sm + 9356;
    float* sB = sm + 25996;
    int* sSrc = (int*)(sm + 42636);
    int* sDst = sSrc + TE;

    const int tid = threadIdx.x;
    const int idx64 = g_idx64;
    const long long* ei64 = (const long long*)ei_raw;
    const int* ei32 = (const int*)ei_raw;

    for (int i = tid; i < 4096; i += TPB) {
        sWe2[i] = We2[i];
        sWm1c[i] = Wm1[128 * 64 + i];
    }
    if (tid < 192) sWe1[tid] = We1[tid];
    if (tid < 64) {
        sbe1[tid] = be1[tid]; sbe2[tid] = be2[tid]; sbm1[tid] = bm1[tid];
    }
    __syncthreads();

    const int wid = tid >> 5, lane = tid & 31;
    const int grp = wid >> 3;                 // 0: edges 0-127, 1: edges 128-255
    const int cb = (wid & 7) * 8;             // channel base (8 channels)
    const int eb = grp * 128 + lane * 4;      // edge base (4 edges)

    for (int tile = blockIdx.x; tile < ntiles; tile += gridDim.x) {
        const int base = tile * TE;

        if (tid < TE) {
            int e = base + tid;
            int s = 0, d = -1;
            if (e < E) {
                if (idx64) { s = (int)ei64[e]; d = (int)ei64[(size_t)E + e]; }
                else       { s = ei32[e];      d = ei32[E + e]; }
                if (s < 0 || s >= N) s = 0;
                if (d < 0 || d >= N) d = 0;
            }
            sSrc[tid] = s;
            sDst[tid] = d;
        }
        __syncthreads();

        // delta = centroids[dst] - centroids[src]
        for (int i = tid; i < 3 * TE; i += TPB) {
            int e = i & (TE - 1), comp = i >> 8;
            int s = sSrc[e], d = sDst[e];
            int dd = (d < 0) ? s : d;
            sDelta[comp * AP + e] =
                cent[(size_t)dd * 3 + comp] - cent[(size_t)s * 3 + comp];
        }
        __syncthreads();

        ull acc[4][4];   // layer scratch accumulator
        ull accm[4][4];  // m1 accumulator (init PQ, finished by L3)

        // L1: e1 = relu(delta @ We1 + be1) -> sA
        zero_acc(acc);
        gemmp(sDelta, AP, sWe1, 3, cb, eb, acc);
        store_relu(sA, acc, sbe1, cb, eb);
        GROUP_BAR(grp);

        // PQ init for m1 (global loads; latency overlapped with L2 gemm)
#pragma unroll
        for (int e = 0; e < 4; ++e) {
            int ed = eb + e;
            int s = sSrc[ed], d = sDst[ed];
            int dd = (d < 0) ? s : d;
            float4 p0 = *reinterpret_cast<const float4*>(&g_P[(size_t)s * 64 + cb]);
            float4 p1 = *reinterpret_cast<const float4*>(&g_P[(size_t)s * 64 + cb + 4]);
            float4 q0 = *reinterpret_cast<const float4*>(&g_Q[(size_t)dd * 64 + cb]);
            float4 q1 = *reinterpret_cast<const float4*>(&g_Q[(size_t)dd * 64 + cb + 4]);
            accm[0][e] = pack2(p0.x + q0.x, p0.y + q0.y);
            accm[1][e] = pack2(p0.z + q0.z, p0.w + q0.w);
            accm[2][e] = pack2(p1.x + q1.x, p1.y + q1.y);
            accm[3][e] = pack2(p1.z + q1.z, p1.w + q1.w);
        }

        // L2: e = relu(e1 @ We2 + be2) -> sB
        zero_acc(acc);
        gemmp(sA, AP, sWe2, 64, cb, eb, acc);
        store_relu(sB, acc, sbe2, cb, eb);
        GROUP_BAR(grp);

        // L3: m1 = relu(e @ Wm1c + PQ + bm1) -> vec4 scatter-add into S1[dst]
        gemmp(sB, AP, sWm1c, 64, cb, eb, accm);
#pragma unroll
        for (int e = 0; e < 4; ++e) {
            int d = sDst[eb + e];
            if (d >= 0) {
                float v[8];
#pragma unroll
                for (int cp = 0; cp < 4; ++cp)
                    unpack2(accm[cp][e], v[2 * cp], v[2 * cp + 1]);
#pragma unroll
                for (int i = 0; i < 8; ++i)
                    v[i] = fmaxf(v[i] + sbm1[cb + i], 0.0f);
                float* p = &S1[(size_t)d * 64 + cb];
                red_add_v4(p, v[0], v[1], v[2], v[3]);
                red_add_v4(p + 4, v[4], v[5], v[6], v[7]);
            }
        }
        if (tid < TE && sDst[tid] >= 0) atomicAdd(&g_cnt[sDst[tid]], 1.0f);
        __syncthreads();
    }
}

// ---- out_kernel ----
// M = (S1 @ Wm2 + cnt*bm2) / max(cnt,1);  out = relu([z, M] @ Wu1 + bu1)
// smem floats: 0: sWu1 8192 | 8192: sWm2 4096 | 12288: bu1 64 | 12352: bm2 64
//              12416: sZM 128*AP = 33280   -> 45696 floats (182,784 B)
__global__ __launch_bounds__(TPB) void out_kernel(
    const float* __restrict__ z, const float* __restrict__ S1,
    const float* __restrict__ Wu1, const float* __restrict__ bu1,
    const float* __restrict__ Wm2, const float* __restrict__ bm2,
    float* __restrict__ out, int N, int ntiles) {
    extern __shared__ float sm[];
    float* sWu1 = sm;
    float* sWm2 = sm + 8192;
    float* sbu1 = sm + 12288;
    float* sbm2 = sm + 12352;
    float* sZM = sm + 12416;

    const int tid = threadIdx.x;
    for (int i = tid; i < 8192; i += TPB) sWu1[i] = Wu1[i];
    for (int i = tid; i < 4096; i += TPB) sWm2[i] = Wm2[i];
    if (tid < 64) { sbu1[tid] = bu1[tid]; sbm2[tid] = bm2[tid]; }
    __syncthreads();

    const int wid = tid >> 5, lane = tid & 31;
    const int grp = wid >> 3;
    const int cb = (wid & 7) * 8;
    const int eb = grp * 128 + lane * 4;

    for (int tile = blockIdx.x; tile < ntiles; tile += gridDim.x) {
        const int base = tile * TE;
        // stage z into rows 0..63, S1 into rows 64..127 (k-major)
        for (int i = tid; i < 64 * TE; i += TPB) {
            int nl = i >> 6, k = i & 63;
            int gn = base + nl;
            float zv = 0.0f, sv = 0.0f;
            if (gn < N) {
                zv = z[(size_t)gn * 64 + k];
                sv = S1[(size_t)gn * 64 + k];
            }
            sZM[k * AP + nl] = zv;
            sZM[(64 + k) * AP + nl] = sv;
        }
        __syncthreads();

        // stage 1: Mpre = S1tile @ Wm2
        ull acc[4][4];
        zero_acc(acc);
        gemmp(sZM + 64 * AP, AP, sWm2, 64, cb, eb, acc);

        // M = (Mpre + cnt*bm2) / max(cnt,1), per node
        float Mv[4][8];
#pragma unroll
        for (int e = 0; e < 4; ++e) {
            int gn = base + eb + e;
            float c = (gn < N) ? g_cnt[gn] : 0.0f;
            float cmax = fmaxf(c, 1.0f);
            float rinv = 1.0f / cmax;
#pragma unroll
            for (int cp = 0; cp < 4; ++cp) {
                float lo, hi;
                unpack2(acc[cp][e], lo, hi);
                Mv[e][2 * cp] = (lo + c * sbm2[cb + 2 * cp]) * rinv;
                Mv[e][2 * cp + 1] = (hi + c * sbm2[cb + 2 * cp + 1]) * rinv;
            }
        }
        __syncthreads();  // everyone done reading rows 64..127

        // write M back into rows 64..127 (k-major)
#pragma unroll
        for (int cp = 0; cp < 4; ++cp) {
            float4 v0 = make_float4(Mv[0][2 * cp], Mv[1][2 * cp],
                                    Mv[2][2 * cp], Mv[3][2 * cp]);
            float4 v1 = make_float4(Mv[0][2 * cp + 1], Mv[1][2 * cp + 1],
                                    Mv[2][2 * cp + 1], Mv[3][2 * cp + 1]);
            *reinterpret_cast<float4*>(sZM + (64 + cb + 2 * cp) * AP + eb) = v0;
            *reinterpret_cast<float4*>(sZM + (64 + cb + 2 * cp + 1) * AP + eb) = v1;
        }
        __syncthreads();

        // stage 2: out = relu([z, M] @ Wu1 + bu1)
        zero_acc(acc);
        gemmp(sZM, AP, sWu1, 128, cb, eb, acc);
#pragma unroll
        for (int e = 0; e < 4; ++e) {
            int gn = base + eb + e;
            if (gn < N) {
                float v[8];
#pragma unroll
                for (int cp = 0; cp < 4; ++cp)
                    unpack2(acc[cp][e], v[2 * cp], v[2 * cp + 1]);
                float4 o0, o1;
                o0.x = fmaxf(v[0] + sbu1[cb + 0], 0.0f);
                o0.y = fmaxf(v[1] + sbu1[cb + 1], 0.0f);
                o0.z = fmaxf(v[2] + sbu1[cb + 2], 0.0f);
                o0.w = fmaxf(v[3] + sbu1[cb + 3], 0.0f);
                o1.x = fmaxf(v[4] + sbu1[cb + 4], 0.0f);
                o1.y = fmaxf(v[5] + sbu1[cb + 5], 0.0f);
                o1.z = fmaxf(v[6] + sbu1[cb + 6], 0.0f);
                o1.w = fmaxf(v[7] + sbu1[cb + 7], 0.0f);
                *reinterpret_cast<float4*>(&out[(size_t)gn * 64 + cb]) = o0;
                *reinterpret_cast<float4*>(&out[(size_t)gn * 64 + cb + 4]) = o1;
            }
        }
        __syncthreads();
    }
}

extern "C" void kernel_launch(void* const* d_in, const int* in_sizes, int n_in,
                              void* d_out, int out_size) {
    const float* z    = (const float*)d_in[0];
    const float* cent = (const float*)d_in[1];
    const void* ei    = d_in[2];
    const float* We1 = (const float*)d_in[3];
    const float* be1 = (const float*)d_in[4];
    const float* We2 = (const float*)d_in[5];
    const float* be2 = (const float*)d_in[6];
    const float* Wm1 = (const float*)d_in[7];
    const float* bm1 = (const float*)d_in[8];
    const float* Wm2 = (const float*)d_in[9];
    const float* bm2 = (const float*)d_in[10];
    const float* Wu1 = (const float*)d_in[11];
    const float* bu1 = (const float*)d_in[12];
    float* out = (float*)d_out;

    const int N = in_sizes[0] / 64;
    const int E = in_sizes[2] / 2;
    const int ntiles_e = (E + TE - 1) / TE;
    const int ntiles_n = (N + TE - 1) / TE;

    const size_t smem_edge = 42636 * sizeof(float) + 2 * TE * sizeof(int);
    const size_t smem_pq   = 24832 * sizeof(float);
    const size_t smem_out  = 45696 * sizeof(float);

    cudaFuncSetAttribute(edge_kernel, cudaFuncAttributeMaxDynamicSharedMemorySize,
                         (int)smem_edge);
    cudaFuncSetAttribute(pq_kernel, cudaFuncAttributeMaxDynamicSharedMemorySize,
                         (int)smem_pq);
    cudaFuncSetAttribute(out_kernel, cudaFuncAttributeMaxDynamicSharedMemorySize,
                         (int)smem_out);

    detect_kernel<<<1, 32>>>((const unsigned long long*)ei);
    zero_kernel<<<(N * 64 + 255) / 256, 256>>>(out, N * 64, N);
    pq_kernel<<<ntiles_n, TPB, smem_pq>>>(z, Wm1, N, ntiles_n);
    edge_kernel<<<148, TPB, smem_edge>>>(cent, ei,
                                         We1, be1, We2, be2,
                                         Wm1, bm1,
                                         out, E, N, ntiles_e);
    out_kernel<<<ntiles_n, TPB, smem_out>>>(z, out, Wu1, bu1, Wm2, bm2,
                                            out, N, ntiles_n);
}